// round 1
// baseline (speedup 1.0000x reference)
#include <cuda_runtime.h>

#define NN 50000
#define NE 1600000

// Scratch (device globals — no allocation allowed)
__device__ __align__(16) float g_h1[NN * 32];
__device__ __align__(16) float g_acc1[NN * 32];
__device__ __align__(16) float g_h2[NN * 64];
__device__ __align__(16) float g_acc2[NN * 64];
__device__ float g_deg[NN];
__device__ float g_pool[64];

__device__ __forceinline__ float lrelu(float v) { return v > 0.f ? v : 0.01f * v; }

__device__ __forceinline__ void red_add_v4(float* p, float a, float b, float c, float d) {
    asm volatile("red.global.add.v4.f32 [%0], {%1,%2,%3,%4};"
                 :: "l"(p), "f"(a), "f"(b), "f"(c), "f"(d) : "memory");
}

// ---------------------------------------------------------------------------
// h1 = x @ W1^T   (x: [N,20], W1: [32,20] row-major) -> g_h1 [N,32]
// ---------------------------------------------------------------------------
__global__ void k_h1(const float* __restrict__ x, const float* __restrict__ W1) {
    __shared__ float W1s[32 * 20];
    __shared__ float xs[128 * 21];   // pad 21 to kill bank conflicts
    const int tid = threadIdx.x;     // 128 threads
    for (int i = tid; i < 32 * 20; i += 128) W1s[i] = W1[i];
    const int base = blockIdx.x * 128;
    for (int i = tid; i < 128 * 20; i += 128) {
        int n = i / 20, k = i % 20;
        int gn = base + n;
        xs[n * 21 + k] = (gn < NN) ? x[gn * 20 + k] : 0.f;
    }
    __syncthreads();
    const int n = base + tid;
    if (n >= NN) return;
    float xr[20];
#pragma unroll
    for (int k = 0; k < 20; k++) xr[k] = xs[tid * 21 + k];
#pragma unroll
    for (int j = 0; j < 32; j += 4) {
        float a0 = 0.f, a1 = 0.f, a2 = 0.f, a3 = 0.f;
#pragma unroll
        for (int k = 0; k < 20; k++) {
            a0 = fmaf(xr[k], W1s[(j + 0) * 20 + k], a0);
            a1 = fmaf(xr[k], W1s[(j + 1) * 20 + k], a1);
            a2 = fmaf(xr[k], W1s[(j + 2) * 20 + k], a2);
            a3 = fmaf(xr[k], W1s[(j + 3) * 20 + k], a3);
        }
        float4 o = make_float4(a0, a1, a2, a3);
        *reinterpret_cast<float4*>(g_h1 + n * 32 + j) = o;
    }
}

// ---------------------------------------------------------------------------
// Edge layer 1: acc1[row] += lrelu(w * h1[col] + b1);  deg[row] += 1
// 8 threads per edge, each handles a float4 slice of the 32-wide row.
// ---------------------------------------------------------------------------
__global__ void k_edge1(const int* __restrict__ edge, const float* __restrict__ weight,
                        const float* __restrict__ b1, int E) {
    const int idx = blockIdx.x * blockDim.x + threadIdx.x;
    if (idx >= E * 8) return;
    const int e = idx >> 3, q = idx & 7;
    const int r = __ldg(edge + e);
    const int c = __ldg(edge + E + e);
    const float w = __ldg(weight + e);
    const float4 h = *reinterpret_cast<const float4*>(g_h1 + c * 32 + q * 4);
    const float4 b = __ldg(reinterpret_cast<const float4*>(b1) + q);
    float m0 = lrelu(fmaf(w, h.x, b.x));
    float m1 = lrelu(fmaf(w, h.y, b.y));
    float m2 = lrelu(fmaf(w, h.z, b.z));
    float m3 = lrelu(fmaf(w, h.w, b.w));
    red_add_v4(g_acc1 + r * 32 + q * 4, m0, m1, m2, m3);
    if (q == 0) atomicAdd(&g_deg[r], 1.f);
}

// ---------------------------------------------------------------------------
// out1 = acc1/max(deg,1) + lrelu(h1 + b1)  (kept in smem only)
// h2   = out1 @ W3^T   (W3: [64,32]) -> g_h2 [N,64]
// One warp per node; W3 staged transposed in smem.
// ---------------------------------------------------------------------------
__global__ void k_h2(const float* __restrict__ b1, const float* __restrict__ W3) {
    __shared__ float W3s[32 * 64];   // [k][j]
    __shared__ float sOut[8][33];
    const int tid = threadIdx.x;     // 256 threads = 8 warps = 8 nodes
    for (int i = tid; i < 64 * 32; i += 256) {
        int j = i / 32, k = i % 32;
        W3s[k * 64 + j] = W3[i];
    }
    __syncthreads();
    const int w = tid >> 5, lane = tid & 31;
    const int n = blockIdx.x * 8 + w;
    if (n < NN) {
        float deg = fmaxf(__ldg(&g_deg[n]), 1.f);
        float o = g_acc1[n * 32 + lane] / deg +
                  lrelu(g_h1[n * 32 + lane] + __ldg(b1 + lane));
        sOut[w][lane] = o;
    }
    __syncwarp();
    if (n >= NN) return;
    float a0 = 0.f, a1 = 0.f;
#pragma unroll
    for (int k = 0; k < 32; k++) {
        float ov = sOut[w][k];
        a0 = fmaf(ov, W3s[k * 64 + lane], a0);
        a1 = fmaf(ov, W3s[k * 64 + 32 + lane], a1);
    }
    g_h2[n * 64 + lane] = a0;
    g_h2[n * 64 + 32 + lane] = a1;
}

// ---------------------------------------------------------------------------
// Edge layer 2: acc2[row] += lrelu(w * h2[col] + b3)
// 16 threads per edge, float4 slices of the 64-wide row.
// ---------------------------------------------------------------------------
__global__ void k_edge2(const int* __restrict__ edge, const float* __restrict__ weight,
                        const float* __restrict__ b3, int E) {
    const int idx = blockIdx.x * blockDim.x + threadIdx.x;
    if (idx >= E * 16) return;
    const int e = idx >> 4, q = idx & 15;
    const int r = __ldg(edge + e);
    const int c = __ldg(edge + E + e);
    const float w = __ldg(weight + e);
    const float4 h = *reinterpret_cast<const float4*>(g_h2 + c * 64 + q * 4);
    const float4 b = __ldg(reinterpret_cast<const float4*>(b3) + q);
    float m0 = lrelu(fmaf(w, h.x, b.x));
    float m1 = lrelu(fmaf(w, h.y, b.y));
    float m2 = lrelu(fmaf(w, h.z, b.z));
    float m3 = lrelu(fmaf(w, h.w, b.w));
    red_add_v4(g_acc2 + r * 64 + q * 4, m0, m1, m2, m3);
}

// ---------------------------------------------------------------------------
// out2 = acc2/max(deg,1) + lrelu(h2 + b3); pooled sum over nodes into g_pool
// ---------------------------------------------------------------------------
__global__ void k_pool(const float* __restrict__ b3) {
    __shared__ float sp[256];
    const int tid = threadIdx.x;       // 256 threads: 4 node-slots x 64 cols
    const int j = tid & 63, s = tid >> 6;
    const float bj = __ldg(b3 + j);
    float local = 0.f;
    for (int n = blockIdx.x * 4 + s; n < NN; n += gridDim.x * 4) {
        float deg = fmaxf(__ldg(&g_deg[n]), 1.f);
        local += g_acc2[n * 64 + j] / deg + lrelu(g_h2[n * 64 + j] + bj);
    }
    sp[tid] = local;
    __syncthreads();
    if (tid < 64)
        atomicAdd(&g_pool[tid], sp[tid] + sp[tid + 64] + sp[tid + 128] + sp[tid + 192]);
}

// ---------------------------------------------------------------------------
// logits = (pool/N) @ W7^T + b7 ; log_softmax -> out[2]
// ---------------------------------------------------------------------------
__global__ void k_final(const float* __restrict__ W7, const float* __restrict__ b7,
                        float* __restrict__ out) {
    if (threadIdx.x == 0) {
        const float inv = 1.f / (float)NN;
        float l0 = b7[0], l1 = b7[1];
#pragma unroll
        for (int j = 0; j < 64; j++) {
            float p = g_pool[j] * inv;
            l0 = fmaf(p, W7[j], l0);
            l1 = fmaf(p, W7[64 + j], l1);
        }
        float m = fmaxf(l0, l1);
        float lse = m + logf(expf(l0 - m) + expf(l1 - m));
        out[0] = l0 - lse;
        out[1] = l1 - lse;
    }
}

extern "C" void kernel_launch(void* const* d_in, const int* in_sizes, int n_in,
                              void* d_out, int out_size) {
    const float* x      = (const float*)d_in[0];
    const int*   edge   = (const int*)d_in[1];
    const float* weight = (const float*)d_in[2];
    const float* W1     = (const float*)d_in[3];
    const float* b1     = (const float*)d_in[4];
    const float* W3     = (const float*)d_in[5];
    const float* b3     = (const float*)d_in[6];
    const float* W7     = (const float*)d_in[7];
    const float* b7     = (const float*)d_in[8];
    const int E = in_sizes[2];

    void *pa1, *pa2, *pdg, *ppl;
    cudaGetSymbolAddress(&pa1, g_acc1);
    cudaGetSymbolAddress(&pa2, g_acc2);
    cudaGetSymbolAddress(&pdg, g_deg);
    cudaGetSymbolAddress(&ppl, g_pool);
    cudaMemsetAsync(pa1, 0, sizeof(float) * NN * 32);
    cudaMemsetAsync(pa2, 0, sizeof(float) * NN * 64);
    cudaMemsetAsync(pdg, 0, sizeof(float) * NN);
    cudaMemsetAsync(ppl, 0, sizeof(float) * 64);

    k_h1<<<(NN + 127) / 128, 128>>>(x, W1);
    k_edge1<<<(E * 8 + 255) / 256, 256>>>(edge, weight, b1, E);
    k_h2<<<(NN + 7) / 8, 256>>>(b1, W3);
    k_edge2<<<(E * 16 + 255) / 256, 256>>>(edge, weight, b3, E);
    k_pool<<<256, 256>>>(b3);
    k_final<<<1, 32>>>(W7, b7, (float*)d_out);
}

// round 2
// speedup vs baseline: 1.0982x; 1.0982x over previous
#include <cuda_runtime.h>

#define NN 50000
#define NE 1600000

// Scratch (device globals — no allocation allowed)
__device__ __align__(16) float g_h1[NN * 32];
__device__ __align__(16) float g_h2[NN * 64];
__device__ int g_cnt[NN];
__device__ int g_rowptr[NN + 1];
__device__ int g_cursor[NN];
__device__ unsigned long long g_csr[NE];   // packed {col, weight}
__device__ float g_pool[64];

__device__ __forceinline__ float lrelu(float v) { return v > 0.f ? v : 0.01f * v; }

// ---------------------------------------------------------------------------
// h1 = x @ W1^T   (x: [N,20], W1: [32,20]) -> g_h1 [N,32]
// ---------------------------------------------------------------------------
__global__ void k_h1(const float* __restrict__ x, const float* __restrict__ W1) {
    __shared__ float W1s[32 * 20];
    __shared__ float xs[128 * 21];
    const int tid = threadIdx.x;     // 128
    for (int i = tid; i < 32 * 20; i += 128) W1s[i] = W1[i];
    const int base = blockIdx.x * 128;
    for (int i = tid; i < 128 * 20; i += 128) {
        int n = i / 20, k = i % 20;
        int gn = base + n;
        xs[n * 21 + k] = (gn < NN) ? x[gn * 20 + k] : 0.f;
    }
    __syncthreads();
    const int n = base + tid;
    if (n >= NN) return;
    float xr[20];
#pragma unroll
    for (int k = 0; k < 20; k++) xr[k] = xs[tid * 21 + k];
#pragma unroll
    for (int j = 0; j < 32; j += 4) {
        float a0 = 0.f, a1 = 0.f, a2 = 0.f, a3 = 0.f;
#pragma unroll
        for (int k = 0; k < 20; k++) {
            a0 = fmaf(xr[k], W1s[(j + 0) * 20 + k], a0);
            a1 = fmaf(xr[k], W1s[(j + 1) * 20 + k], a1);
            a2 = fmaf(xr[k], W1s[(j + 2) * 20 + k], a2);
            a3 = fmaf(xr[k], W1s[(j + 3) * 20 + k], a3);
        }
        *reinterpret_cast<float4*>(g_h1 + n * 32 + j) = make_float4(a0, a1, a2, a3);
    }
}

// ---------------------------------------------------------------------------
// CSR build: histogram, scan, scatter
// ---------------------------------------------------------------------------
__global__ void k_hist(const int* __restrict__ edge, int E) {
    int i = blockIdx.x * blockDim.x + threadIdx.x;
    if (i < E) atomicAdd(&g_cnt[__ldg(edge + i)], 1);
}

__global__ void k_scan() {          // single block, 1024 threads
    __shared__ int wsum[32];
    const int tid = threadIdx.x, lane = tid & 31, wid = tid >> 5;
    int carry = 0;
    for (int base = 0; base < NN; base += 1024) {
        int i = base + tid;
        int v = (i < NN) ? g_cnt[i] : 0;
        int incl = v;
#pragma unroll
        for (int off = 1; off < 32; off <<= 1) {
            int t = __shfl_up_sync(0xffffffffu, incl, off);
            if (lane >= off) incl += t;
        }
        if (lane == 31) wsum[wid] = incl;
        __syncthreads();
        if (wid == 0) {
            int s = wsum[lane];
#pragma unroll
            for (int off = 1; off < 32; off <<= 1) {
                int t = __shfl_up_sync(0xffffffffu, s, off);
                if (lane >= off) s += t;
            }
            wsum[lane] = s;
        }
        __syncthreads();
        int woff = (wid > 0) ? wsum[wid - 1] : 0;
        int excl = carry + woff + incl - v;
        if (i < NN) { g_rowptr[i] = excl; g_cursor[i] = excl; }
        carry += wsum[31];
        __syncthreads();
    }
    if (tid == 0) g_rowptr[NN] = carry;
}

__global__ void k_scatter(const int* __restrict__ edge, const float* __restrict__ weight, int E) {
    int e = blockIdx.x * blockDim.x + threadIdx.x;
    if (e >= E) return;
    int r = __ldg(edge + e);
    int c = __ldg(edge + E + e);
    float w = __ldg(weight + e);
    int pos = atomicAdd(&g_cursor[r], 1);
    g_csr[pos] = (unsigned long long)(unsigned)c |
                 ((unsigned long long)__float_as_uint(w) << 32);
}

// ---------------------------------------------------------------------------
// Layer 1 (CSR, warp per node) fused with W3 GEMM:
//   acc = sum lrelu(w*h1[col] + b1); out1 = acc/deg + lrelu(h1[n]+b1)
//   h2[n] = out1 @ W3^T
// ---------------------------------------------------------------------------
__global__ void __launch_bounds__(256) k_l1(const float* __restrict__ b1,
                                            const float* __restrict__ W3) {
    __shared__ float W3s[32 * 64];   // [k][j]
    const int tid = threadIdx.x;     // 8 warps
    for (int i = tid; i < 64 * 32; i += 256) {
        int j = i >> 5, k = i & 31;
        W3s[k * 64 + j] = W3[i];
    }
    __syncthreads();
    const int wid = tid >> 5, lane = tid & 31;
    const int n = blockIdx.x * 8 + wid;
    if (n >= NN) return;
    const int start = g_rowptr[n], end = g_rowptr[n + 1];
    const float bl = __ldg(b1 + lane);
    float acc = 0.f;
    int i = start;
    for (; i + 4 <= end; i += 4) {
        unsigned long long e0 = __ldg(g_csr + i);
        unsigned long long e1 = __ldg(g_csr + i + 1);
        unsigned long long e2 = __ldg(g_csr + i + 2);
        unsigned long long e3 = __ldg(g_csr + i + 3);
        float h0 = __ldg(g_h1 + (int)(unsigned)e0 * 32 + lane);
        float h1v = __ldg(g_h1 + (int)(unsigned)e1 * 32 + lane);
        float h2v = __ldg(g_h1 + (int)(unsigned)e2 * 32 + lane);
        float h3 = __ldg(g_h1 + (int)(unsigned)e3 * 32 + lane);
        acc += lrelu(fmaf(__uint_as_float((unsigned)(e0 >> 32)), h0, bl));
        acc += lrelu(fmaf(__uint_as_float((unsigned)(e1 >> 32)), h1v, bl));
        acc += lrelu(fmaf(__uint_as_float((unsigned)(e2 >> 32)), h2v, bl));
        acc += lrelu(fmaf(__uint_as_float((unsigned)(e3 >> 32)), h3, bl));
    }
    for (; i < end; i++) {
        unsigned long long e0 = __ldg(g_csr + i);
        float h0 = __ldg(g_h1 + (int)(unsigned)e0 * 32 + lane);
        acc += lrelu(fmaf(__uint_as_float((unsigned)(e0 >> 32)), h0, bl));
    }
    float deg = fmaxf((float)(end - start), 1.f);
    float out1 = acc / deg + lrelu(g_h1[n * 32 + lane] + bl);
    // GEMM: h2[n][j] = sum_k out1[k] * W3[j][k]
    float a0 = 0.f, a1 = 0.f;
#pragma unroll
    for (int k = 0; k < 32; k++) {
        float ov = __shfl_sync(0xffffffffu, out1, k);
        a0 = fmaf(ov, W3s[k * 64 + lane], a0);
        a1 = fmaf(ov, W3s[k * 64 + 32 + lane], a1);
    }
    g_h2[n * 64 + lane] = a0;
    g_h2[n * 64 + 32 + lane] = a1;
}

// ---------------------------------------------------------------------------
// Layer 2 (CSR, warp per node) fused with global mean pool:
//   acc = sum lrelu(w*h2[col] + b3); out2 = acc/deg + lrelu(h2[n]+b3)
//   pool += out2  (block-reduced, then atomic)
// ---------------------------------------------------------------------------
__global__ void __launch_bounds__(256) k_l2(const float* __restrict__ b3) {
    __shared__ float sp[8][64];
    const int tid = threadIdx.x;     // 8 warps
    const int wid = tid >> 5, lane = tid & 31;
    const int n = blockIdx.x * 8 + wid;
    float2 o = make_float2(0.f, 0.f);
    if (n < NN) {
        const int start = g_rowptr[n], end = g_rowptr[n + 1];
        const float2 bl = __ldg(reinterpret_cast<const float2*>(b3) + lane);
        float ax = 0.f, ay = 0.f;
        int i = start;
        for (; i + 4 <= end; i += 4) {
            unsigned long long e0 = __ldg(g_csr + i);
            unsigned long long e1 = __ldg(g_csr + i + 1);
            unsigned long long e2 = __ldg(g_csr + i + 2);
            unsigned long long e3 = __ldg(g_csr + i + 3);
            float2 h0 = *reinterpret_cast<const float2*>(g_h2 + (int)(unsigned)e0 * 64 + lane * 2);
            float2 h1v = *reinterpret_cast<const float2*>(g_h2 + (int)(unsigned)e1 * 64 + lane * 2);
            float2 h2v = *reinterpret_cast<const float2*>(g_h2 + (int)(unsigned)e2 * 64 + lane * 2);
            float2 h3 = *reinterpret_cast<const float2*>(g_h2 + (int)(unsigned)e3 * 64 + lane * 2);
            float w0 = __uint_as_float((unsigned)(e0 >> 32));
            float w1 = __uint_as_float((unsigned)(e1 >> 32));
            float w2 = __uint_as_float((unsigned)(e2 >> 32));
            float w3 = __uint_as_float((unsigned)(e3 >> 32));
            ax += lrelu(fmaf(w0, h0.x, bl.x)) + lrelu(fmaf(w1, h1v.x, bl.x))
                + lrelu(fmaf(w2, h2v.x, bl.x)) + lrelu(fmaf(w3, h3.x, bl.x));
            ay += lrelu(fmaf(w0, h0.y, bl.y)) + lrelu(fmaf(w1, h1v.y, bl.y))
                + lrelu(fmaf(w2, h2v.y, bl.y)) + lrelu(fmaf(w3, h3.y, bl.y));
        }
        for (; i < end; i++) {
            unsigned long long e0 = __ldg(g_csr + i);
            float2 h0 = *reinterpret_cast<const float2*>(g_h2 + (int)(unsigned)e0 * 64 + lane * 2);
            float w0 = __uint_as_float((unsigned)(e0 >> 32));
            ax += lrelu(fmaf(w0, h0.x, bl.x));
            ay += lrelu(fmaf(w0, h0.y, bl.y));
        }
        float deg = fmaxf((float)(end - start), 1.f);
        float2 hs = *reinterpret_cast<const float2*>(g_h2 + n * 64 + lane * 2);
        o.x = ax / deg + lrelu(hs.x + bl.x);
        o.y = ay / deg + lrelu(hs.y + bl.y);
    }
    sp[wid][lane * 2] = o.x;
    sp[wid][lane * 2 + 1] = o.y;
    __syncthreads();
    if (tid < 64) {
        float s = 0.f;
#pragma unroll
        for (int w = 0; w < 8; w++) s += sp[w][tid];
        atomicAdd(&g_pool[tid], s);
    }
}

// ---------------------------------------------------------------------------
// logits = (pool/N) @ W7^T + b7 ; log_softmax -> out[2]
// ---------------------------------------------------------------------------
__global__ void k_final(const float* __restrict__ W7, const float* __restrict__ b7,
                        float* __restrict__ out) {
    if (threadIdx.x == 0) {
        const float inv = 1.f / (float)NN;
        float l0 = b7[0], l1 = b7[1];
#pragma unroll
        for (int j = 0; j < 64; j++) {
            float p = g_pool[j] * inv;
            l0 = fmaf(p, W7[j], l0);
            l1 = fmaf(p, W7[64 + j], l1);
        }
        float m = fmaxf(l0, l1);
        float lse = m + logf(expf(l0 - m) + expf(l1 - m));
        out[0] = l0 - lse;
        out[1] = l1 - lse;
    }
}

extern "C" void kernel_launch(void* const* d_in, const int* in_sizes, int n_in,
                              void* d_out, int out_size) {
    const float* x      = (const float*)d_in[0];
    const int*   edge   = (const int*)d_in[1];
    const float* weight = (const float*)d_in[2];
    const float* W1     = (const float*)d_in[3];
    const float* b1     = (const float*)d_in[4];
    const float* W3     = (const float*)d_in[5];
    const float* b3     = (const float*)d_in[6];
    const float* W7     = (const float*)d_in[7];
    const float* b7     = (const float*)d_in[8];
    const int E = in_sizes[2];

    void *pcnt, *ppl;
    cudaGetSymbolAddress(&pcnt, g_cnt);
    cudaGetSymbolAddress(&ppl, g_pool);
    cudaMemsetAsync(pcnt, 0, sizeof(int) * NN);
    cudaMemsetAsync(ppl, 0, sizeof(float) * 64);

    k_h1<<<(NN + 127) / 128, 128>>>(x, W1);
    k_hist<<<(E + 511) / 512, 512>>>(edge, E);
    k_scan<<<1, 1024>>>();
    k_scatter<<<(E + 255) / 256, 256>>>(edge, weight, E);
    k_l1<<<(NN + 7) / 8, 256>>>(b1, W3);
    k_l2<<<(NN + 7) / 8, 256>>>(b3);
    k_final<<<1, 32>>>(W7, b7, (float*)d_out);
}

// round 3
// speedup vs baseline: 1.2953x; 1.1795x over previous
#include <cuda_runtime.h>
#include <cuda_fp16.h>

#define NN 50000
#define NE 1600000
#define SCAN_BLK 1024
#define N_SBLK ((NN + SCAN_BLK - 1) / SCAN_BLK)   // 49

// Scratch (device globals — no allocation allowed)
__device__ __align__(16) __half g_h1h[NN * 32];
__device__ __align__(16) __half g_h2h[NN * 64];
__device__ int g_cnt[NN];
__device__ int g_rank[NE];
__device__ int g_rowptr[NN + 1];
__device__ int g_bsum[N_SBLK];
__device__ int g_boff[N_SBLK];
__device__ unsigned long long g_csr[NE];   // packed {col, weight(fp32 bits)}
__device__ float g_pool[64];

__device__ __forceinline__ float lrelu(float v) { return v > 0.f ? v : 0.01f * v; }

// ---------------------------------------------------------------------------
// h1 = x @ W1^T  (x:[N,20], W1:[32,20]) -> g_h1h [N,32] fp16
// ---------------------------------------------------------------------------
__global__ void k_h1(const float* __restrict__ x, const float* __restrict__ W1) {
    __shared__ float W1s[32 * 20];
    __shared__ float xs[128 * 21];
    const int tid = threadIdx.x;     // 128
    for (int i = tid; i < 32 * 20; i += 128) W1s[i] = W1[i];
    const int base = blockIdx.x * 128;
    for (int i = tid; i < 128 * 20; i += 128) {
        int n = i / 20, k = i % 20;
        int gn = base + n;
        xs[n * 21 + k] = (gn < NN) ? x[gn * 20 + k] : 0.f;
    }
    __syncthreads();
    const int n = base + tid;
    if (n >= NN) return;
    float xr[20];
#pragma unroll
    for (int k = 0; k < 20; k++) xr[k] = xs[tid * 21 + k];
#pragma unroll
    for (int j = 0; j < 32; j += 4) {
        float a0 = 0.f, a1 = 0.f, a2 = 0.f, a3 = 0.f;
#pragma unroll
        for (int k = 0; k < 20; k++) {
            a0 = fmaf(xr[k], W1s[(j + 0) * 20 + k], a0);
            a1 = fmaf(xr[k], W1s[(j + 1) * 20 + k], a1);
            a2 = fmaf(xr[k], W1s[(j + 2) * 20 + k], a2);
            a3 = fmaf(xr[k], W1s[(j + 3) * 20 + k], a3);
        }
        *reinterpret_cast<__half2*>(g_h1h + n * 32 + j)     = __floats2half2_rn(a0, a1);
        *reinterpret_cast<__half2*>(g_h1h + n * 32 + j + 2) = __floats2half2_rn(a2, a3);
    }
}

// ---------------------------------------------------------------------------
// CSR build
// ---------------------------------------------------------------------------
__global__ void k_hist(const int* __restrict__ edge, int E) {
    int i = blockIdx.x * blockDim.x + threadIdx.x;
    if (i < E) g_rank[i] = atomicAdd(&g_cnt[__ldg(edge + i)], 1);
}

__global__ void k_scanA() {          // N_SBLK blocks x 1024 threads
    __shared__ int wsum[32];
    const int tid = threadIdx.x, lane = tid & 31, wid = tid >> 5;
    const int i = blockIdx.x * SCAN_BLK + tid;
    int v = (i < NN) ? g_cnt[i] : 0;
    int incl = v;
#pragma unroll
    for (int off = 1; off < 32; off <<= 1) {
        int t = __shfl_up_sync(0xffffffffu, incl, off);
        if (lane >= off) incl += t;
    }
    if (lane == 31) wsum[wid] = incl;
    __syncthreads();
    if (wid == 0) {
        int s = wsum[lane];
#pragma unroll
        for (int off = 1; off < 32; off <<= 1) {
            int t = __shfl_up_sync(0xffffffffu, s, off);
            if (lane >= off) s += t;
        }
        wsum[lane] = s;
    }
    __syncthreads();
    int woff = (wid > 0) ? wsum[wid - 1] : 0;
    if (i < NN) g_rowptr[i] = woff + incl - v;    // block-local exclusive
    if (tid == SCAN_BLK - 1) g_bsum[blockIdx.x] = woff + incl;
}

__global__ void k_scanB() {          // 1 thread, trivial (N_SBLK = 49)
    if (threadIdx.x == 0) {
        int carry = 0;
        for (int b = 0; b < N_SBLK; b++) { g_boff[b] = carry; carry += g_bsum[b]; }
        g_rowptr[NN] = carry;
    }
}

__global__ void k_scanC() {
    int i = blockIdx.x * blockDim.x + threadIdx.x;
    if (i < NN) g_rowptr[i] += g_boff[i >> 10];
}

__global__ void k_scatter(const int* __restrict__ edge, const float* __restrict__ weight, int E) {
    int e = blockIdx.x * blockDim.x + threadIdx.x;
    if (e >= E) return;
    int r = __ldg(edge + e);
    int c = __ldg(edge + E + e);
    float w = __ldg(weight + e);
    int pos = __ldg(&g_rowptr[r]) + g_rank[e];
    g_csr[pos] = (unsigned long long)(unsigned)c |
                 ((unsigned long long)__float_as_uint(w) << 32);
}

// ---------------------------------------------------------------------------
// Layer 1 (CSR, warp/node) fused with W3 GEMM -> g_h2h fp16
// ---------------------------------------------------------------------------
__global__ void __launch_bounds__(256) k_l1(const float* __restrict__ b1,
                                            const float* __restrict__ W3) {
    __shared__ float W3s[32 * 64];   // [k][j]
    const int tid = threadIdx.x;     // 8 warps
    for (int i = tid; i < 64 * 32; i += 256) {
        int j = i >> 5, k = i & 31;
        W3s[k * 64 + j] = W3[i];
    }
    __syncthreads();
    const int wid = tid >> 5, lane = tid & 31;
    const int n = blockIdx.x * 8 + wid;
    if (n >= NN) return;
    const int start = g_rowptr[n], end = g_rowptr[n + 1];
    const float bl = __ldg(b1 + lane);
    float acc = 0.f;
    int i = start;
    for (; i + 4 <= end; i += 4) {
        unsigned long long e0 = __ldg(g_csr + i);
        unsigned long long e1 = __ldg(g_csr + i + 1);
        unsigned long long e2 = __ldg(g_csr + i + 2);
        unsigned long long e3 = __ldg(g_csr + i + 3);
        float h0 = __half2float(__ldg(g_h1h + (int)(unsigned)e0 * 32 + lane));
        float h1v = __half2float(__ldg(g_h1h + (int)(unsigned)e1 * 32 + lane));
        float h2v = __half2float(__ldg(g_h1h + (int)(unsigned)e2 * 32 + lane));
        float h3 = __half2float(__ldg(g_h1h + (int)(unsigned)e3 * 32 + lane));
        acc += lrelu(fmaf(__uint_as_float((unsigned)(e0 >> 32)), h0, bl));
        acc += lrelu(fmaf(__uint_as_float((unsigned)(e1 >> 32)), h1v, bl));
        acc += lrelu(fmaf(__uint_as_float((unsigned)(e2 >> 32)), h2v, bl));
        acc += lrelu(fmaf(__uint_as_float((unsigned)(e3 >> 32)), h3, bl));
    }
    for (; i < end; i++) {
        unsigned long long e0 = __ldg(g_csr + i);
        float h0 = __half2float(__ldg(g_h1h + (int)(unsigned)e0 * 32 + lane));
        acc += lrelu(fmaf(__uint_as_float((unsigned)(e0 >> 32)), h0, bl));
    }
    float deg = fmaxf((float)(end - start), 1.f);
    float out1 = acc / deg + lrelu(__half2float(g_h1h[n * 32 + lane]) + bl);
    float a0 = 0.f, a1 = 0.f;
#pragma unroll
    for (int k = 0; k < 32; k++) {
        float ov = __shfl_sync(0xffffffffu, out1, k);
        a0 = fmaf(ov, W3s[k * 64 + lane], a0);
        a1 = fmaf(ov, W3s[k * 64 + 32 + lane], a1);
    }
    g_h2h[n * 64 + lane]      = __float2half_rn(a0);
    g_h2h[n * 64 + 32 + lane] = __float2half_rn(a1);
}

// ---------------------------------------------------------------------------
// Layer 2 (CSR, warp/node) fused with global mean pool
// ---------------------------------------------------------------------------
__global__ void __launch_bounds__(256) k_l2(const float* __restrict__ b3) {
    __shared__ float sp[8][64];
    const int tid = threadIdx.x;     // 8 warps
    const int wid = tid >> 5, lane = tid & 31;
    const int n = blockIdx.x * 8 + wid;
    float ox = 0.f, oy = 0.f;
    if (n < NN) {
        const int start = g_rowptr[n], end = g_rowptr[n + 1];
        const float2 bl = __ldg(reinterpret_cast<const float2*>(b3) + lane);
        float ax = 0.f, ay = 0.f;
        int i = start;
        for (; i + 4 <= end; i += 4) {
            unsigned long long e0 = __ldg(g_csr + i);
            unsigned long long e1 = __ldg(g_csr + i + 1);
            unsigned long long e2 = __ldg(g_csr + i + 2);
            unsigned long long e3 = __ldg(g_csr + i + 3);
            float2 h0 = __half22float2(__ldg(reinterpret_cast<const __half2*>(g_h2h + (int)(unsigned)e0 * 64 + lane * 2)));
            float2 h1v = __half22float2(__ldg(reinterpret_cast<const __half2*>(g_h2h + (int)(unsigned)e1 * 64 + lane * 2)));
            float2 h2v = __half22float2(__ldg(reinterpret_cast<const __half2*>(g_h2h + (int)(unsigned)e2 * 64 + lane * 2)));
            float2 h3 = __half22float2(__ldg(reinterpret_cast<const __half2*>(g_h2h + (int)(unsigned)e3 * 64 + lane * 2)));
            float w0 = __uint_as_float((unsigned)(e0 >> 32));
            float w1 = __uint_as_float((unsigned)(e1 >> 32));
            float w2 = __uint_as_float((unsigned)(e2 >> 32));
            float w3 = __uint_as_float((unsigned)(e3 >> 32));
            ax += lrelu(fmaf(w0, h0.x, bl.x)) + lrelu(fmaf(w1, h1v.x, bl.x))
                + lrelu(fmaf(w2, h2v.x, bl.x)) + lrelu(fmaf(w3, h3.x, bl.x));
            ay += lrelu(fmaf(w0, h0.y, bl.y)) + lrelu(fmaf(w1, h1v.y, bl.y))
                + lrelu(fmaf(w2, h2v.y, bl.y)) + lrelu(fmaf(w3, h3.y, bl.y));
        }
        for (; i < end; i++) {
            unsigned long long e0 = __ldg(g_csr + i);
            float2 h0 = __half22float2(__ldg(reinterpret_cast<const __half2*>(g_h2h + (int)(unsigned)e0 * 64 + lane * 2)));
            float w0 = __uint_as_float((unsigned)(e0 >> 32));
            ax += lrelu(fmaf(w0, h0.x, bl.x));
            ay += lrelu(fmaf(w0, h0.y, bl.y));
        }
        float deg = fmaxf((float)(end - start), 1.f);
        float2 hs = __half22float2(*reinterpret_cast<const __half2*>(g_h2h + n * 64 + lane * 2));
        ox = ax / deg + lrelu(hs.x + bl.x);
        oy = ay / deg + lrelu(hs.y + bl.y);
    }
    sp[wid][lane * 2] = ox;
    sp[wid][lane * 2 + 1] = oy;
    __syncthreads();
    if (tid < 64) {
        float s = 0.f;
#pragma unroll
        for (int w = 0; w < 8; w++) s += sp[w][tid];
        atomicAdd(&g_pool[tid], s);
    }
}

// ---------------------------------------------------------------------------
// logits = (pool/N) @ W7^T + b7 ; log_softmax -> out[2]
// ---------------------------------------------------------------------------
__global__ void k_final(const float* __restrict__ W7, const float* __restrict__ b7,
                        float* __restrict__ out) {
    if (threadIdx.x == 0) {
        const float inv = 1.f / (float)NN;
        float l0 = b7[0], l1 = b7[1];
#pragma unroll
        for (int j = 0; j < 64; j++) {
            float p = g_pool[j] * inv;
            l0 = fmaf(p, W7[j], l0);
            l1 = fmaf(p, W7[64 + j], l1);
        }
        float m = fmaxf(l0, l1);
        float lse = m + logf(expf(l0 - m) + expf(l1 - m));
        out[0] = l0 - lse;
        out[1] = l1 - lse;
    }
}

extern "C" void kernel_launch(void* const* d_in, const int* in_sizes, int n_in,
                              void* d_out, int out_size) {
    const float* x      = (const float*)d_in[0];
    const int*   edge   = (const int*)d_in[1];
    const float* weight = (const float*)d_in[2];
    const float* W1     = (const float*)d_in[3];
    const float* b1     = (const float*)d_in[4];
    const float* W3     = (const float*)d_in[5];
    const float* b3     = (const float*)d_in[6];
    const float* W7     = (const float*)d_in[7];
    const float* b7     = (const float*)d_in[8];
    const int E = in_sizes[2];

    void *pcnt, *ppl;
    cudaGetSymbolAddress(&pcnt, g_cnt);
    cudaGetSymbolAddress(&ppl, g_pool);
    cudaMemsetAsync(pcnt, 0, sizeof(int) * NN);
    cudaMemsetAsync(ppl, 0, sizeof(float) * 64);

    k_h1<<<(NN + 127) / 128, 128>>>(x, W1);
    k_hist<<<(E + 511) / 512, 512>>>(edge, E);
    k_scanA<<<N_SBLK, SCAN_BLK>>>();
    k_scanB<<<1, 32>>>();
    k_scanC<<<(NN + 1023) / 1024, 1024>>>();
    k_scatter<<<(E + 255) / 256, 256>>>(edge, weight, E);
    k_l1<<<(NN + 7) / 8, 256>>>(b1, W3);
    k_l2<<<(NN + 7) / 8, 256>>>(b3);
    k_final<<<1, 32>>>(W7, b7, (float*)d_out);
}

// round 5
// speedup vs baseline: 1.4071x; 1.0863x over previous
#include <cuda_runtime.h>
#include <cuda_fp16.h>

#define NN 50000
#define NE 1600000
#define H1_BLOCKS ((NN + 255) / 256)              // 196
#define SCAN_BLK 1024
#define N_SBLK ((NN + SCAN_BLK - 1) / SCAN_BLK)   // 49

// Scratch (device globals — zero-initialized at load; kernels self-clean so
// every graph replay starts from identical state; no allocation anywhere)
__device__ __align__(16) __half g_h1h[NN * 32];
__device__ __align__(16) __half g_h2h[NN * 64];
__device__ int g_cnt[NN];                 // zeroed by k_scanB after use
__device__ int g_rank[NE];
__device__ int g_rowptr[NN + 1];
__device__ int g_bsum[N_SBLK];
__device__ unsigned long long g_csr[NE];  // packed {col, weight fp32 bits}
__device__ float g_pool[64];              // zeroed by last l2 block
__device__ unsigned g_tick;               // l2 ticket (self-reset)

__device__ __forceinline__ float lrelu(float v) { return v > 0.f ? v : 0.01f * v; }

// ---------------------------------------------------------------------------
// Fused: blocks [0,H1_BLOCKS) compute h1 = x @ W1^T -> fp16
//        blocks [H1_BLOCKS,..) histogram rows + record per-edge rank
// ---------------------------------------------------------------------------
__global__ void __launch_bounds__(256) k_h1hist(const float* __restrict__ x,
                                                const float* __restrict__ W1,
                                                const int* __restrict__ edge, int E) {
    const int tid = threadIdx.x;
    if (blockIdx.x < H1_BLOCKS) {
        __shared__ float W1s[32 * 20];
        __shared__ float xs[256 * 21];
        for (int i = tid; i < 32 * 20; i += 256) W1s[i] = W1[i];
        const int base = blockIdx.x * 256;
        for (int i = tid; i < 256 * 20; i += 256) {
            int gi = base * 20 + i;
            int n = i / 20, k = i % 20;
            xs[n * 21 + k] = (gi < NN * 20) ? x[gi] : 0.f;
        }
        __syncthreads();
        const int n = base + tid;
        if (n >= NN) return;
        float xr[20];
#pragma unroll
        for (int k = 0; k < 20; k++) xr[k] = xs[tid * 21 + k];
#pragma unroll
        for (int j = 0; j < 32; j += 4) {
            float a0 = 0.f, a1 = 0.f, a2 = 0.f, a3 = 0.f;
#pragma unroll
            for (int k = 0; k < 20; k++) {
                a0 = fmaf(xr[k], W1s[(j + 0) * 20 + k], a0);
                a1 = fmaf(xr[k], W1s[(j + 1) * 20 + k], a1);
                a2 = fmaf(xr[k], W1s[(j + 2) * 20 + k], a2);
                a3 = fmaf(xr[k], W1s[(j + 3) * 20 + k], a3);
            }
            *reinterpret_cast<__half2*>(g_h1h + n * 32 + j)     = __floats2half2_rn(a0, a1);
            *reinterpret_cast<__half2*>(g_h1h + n * 32 + j + 2) = __floats2half2_rn(a2, a3);
        }
    } else {
        int i = (blockIdx.x - H1_BLOCKS) * 256 + tid;
        if (i < E) g_rank[i] = atomicAdd(&g_cnt[__ldg(edge + i)], 1);
    }
}

// ---------------------------------------------------------------------------
// Scan pass A: block-local exclusive prefix into g_rowptr, block sums to g_bsum
// ---------------------------------------------------------------------------
__global__ void __launch_bounds__(SCAN_BLK) k_scanA() {
    __shared__ int wsum[32];
    const int tid = threadIdx.x, lane = tid & 31, wid = tid >> 5;
    const int i = blockIdx.x * SCAN_BLK + tid;
    int v = (i < NN) ? g_cnt[i] : 0;
    int incl = v;
#pragma unroll
    for (int off = 1; off < 32; off <<= 1) {
        int t = __shfl_up_sync(0xffffffffu, incl, off);
        if (lane >= off) incl += t;
    }
    if (lane == 31) wsum[wid] = incl;
    __syncthreads();
    if (wid == 0) {
        int s = wsum[lane];
#pragma unroll
        for (int off = 1; off < 32; off <<= 1) {
            int t = __shfl_up_sync(0xffffffffu, s, off);
            if (lane >= off) s += t;
        }
        wsum[lane] = s;
    }
    __syncthreads();
    int woff = (wid > 0) ? wsum[wid - 1] : 0;
    if (i < NN) g_rowptr[i] = woff + incl - v;         // block-local exclusive
    if (tid == SCAN_BLK - 1) g_bsum[blockIdx.x] = woff + incl;
}

// ---------------------------------------------------------------------------
// Scan pass B: each block adds the prefix of earlier block sums (<=49 values,
// trivial serial sum), zeroes g_cnt for the next replay. No inter-block sync.
// ---------------------------------------------------------------------------
__global__ void __launch_bounds__(SCAN_BLK) k_scanB() {
    __shared__ int sOff;
    const int tid = threadIdx.x;
    const int b = blockIdx.x;
    if (tid == 0) {
        int off = 0;
        for (int p = 0; p < b; p++) off += __ldg(&g_bsum[p]);
        sOff = off;
        if (b == N_SBLK - 1) g_rowptr[NN] = off + __ldg(&g_bsum[b]);
    }
    __syncthreads();
    const int i = b * SCAN_BLK + tid;
    if (i < NN) {
        g_rowptr[i] += sOff;
        g_cnt[i] = 0;                                   // self-clean for replay
    }
}

// ---------------------------------------------------------------------------
// Scatter edges into CSR slots (atomic-free: rowptr[r] + rank[e])
// ---------------------------------------------------------------------------
__global__ void k_scatter(const int* __restrict__ edge, const float* __restrict__ weight, int E) {
    int e = blockIdx.x * blockDim.x + threadIdx.x;
    if (e >= E) return;
    int r = __ldg(edge + e);
    int c = __ldg(edge + E + e);
    float w = __ldg(weight + e);
    int pos = __ldg(&g_rowptr[r]) + g_rank[e];
    g_csr[pos] = (unsigned long long)(unsigned)c |
                 ((unsigned long long)__float_as_uint(w) << 32);
}

// ---------------------------------------------------------------------------
// Layer 1 (CSR, warp/node) fused with W3 GEMM -> g_h2h fp16. Unroll 8.
// ---------------------------------------------------------------------------
__global__ void __launch_bounds__(256) k_l1(const float* __restrict__ b1,
                                            const float* __restrict__ W3) {
    __shared__ float W3s[32 * 64];   // [k][j]
    const int tid = threadIdx.x;     // 8 warps
    for (int i = tid; i < 64 * 32; i += 256) {
        int j = i >> 5, k = i & 31;
        W3s[k * 64 + j] = W3[i];
    }
    __syncthreads();
    const int wid = tid >> 5, lane = tid & 31;
    const int n = blockIdx.x * 8 + wid;
    if (n >= NN) return;
    const int start = g_rowptr[n], end = g_rowptr[n + 1];
    const float bl = __ldg(b1 + lane);
    float acc = 0.f;
    int i = start;
    for (; i + 8 <= end; i += 8) {
        unsigned long long e[8];
#pragma unroll
        for (int u = 0; u < 8; u++) e[u] = __ldg(g_csr + i + u);
        float h[8];
#pragma unroll
        for (int u = 0; u < 8; u++)
            h[u] = __half2float(__ldg(g_h1h + (int)(unsigned)e[u] * 32 + lane));
#pragma unroll
        for (int u = 0; u < 8; u++)
            acc += lrelu(fmaf(__uint_as_float((unsigned)(e[u] >> 32)), h[u], bl));
    }
    for (; i < end; i++) {
        unsigned long long e0 = __ldg(g_csr + i);
        float h0 = __half2float(__ldg(g_h1h + (int)(unsigned)e0 * 32 + lane));
        acc += lrelu(fmaf(__uint_as_float((unsigned)(e0 >> 32)), h0, bl));
    }
    float deg = fmaxf((float)(end - start), 1.f);
    float out1 = acc / deg + lrelu(__half2float(g_h1h[n * 32 + lane]) + bl);
    float a0 = 0.f, a1 = 0.f;
#pragma unroll
    for (int k = 0; k < 32; k++) {
        float ov = __shfl_sync(0xffffffffu, out1, k);
        a0 = fmaf(ov, W3s[k * 64 + lane], a0);
        a1 = fmaf(ov, W3s[k * 64 + 32 + lane], a1);
    }
    g_h2h[n * 64 + lane]      = __float2half_rn(a0);
    g_h2h[n * 64 + 32 + lane] = __float2half_rn(a1);
}

// ---------------------------------------------------------------------------
// Layer 2 (CSR, warp/node) + global mean pool + (last block) classifier.
// Self-cleans g_pool and g_tick for graph replay. No spin loops.
// ---------------------------------------------------------------------------
__global__ void __launch_bounds__(256) k_l2(const float* __restrict__ b3,
                                            const float* __restrict__ W7,
                                            const float* __restrict__ b7,
                                            float* __restrict__ out) {
    __shared__ float sp[8][64];
    __shared__ bool sLast;
    const int tid = threadIdx.x;     // 8 warps
    const int wid = tid >> 5, lane = tid & 31;
    const int n = blockIdx.x * 8 + wid;
    float ox = 0.f, oy = 0.f;
    if (n < NN) {
        const int start = g_rowptr[n], end = g_rowptr[n + 1];
        const float2 bl = __ldg(reinterpret_cast<const float2*>(b3) + lane);
        float ax = 0.f, ay = 0.f;
        int i = start;
        for (; i + 8 <= end; i += 8) {
            unsigned long long e[8];
#pragma unroll
            for (int u = 0; u < 8; u++) e[u] = __ldg(g_csr + i + u);
            float2 h[8];
#pragma unroll
            for (int u = 0; u < 8; u++)
                h[u] = __half22float2(__ldg(reinterpret_cast<const __half2*>(
                           g_h2h + (int)(unsigned)e[u] * 64 + lane * 2)));
#pragma unroll
            for (int u = 0; u < 8; u++) {
                float w = __uint_as_float((unsigned)(e[u] >> 32));
                ax += lrelu(fmaf(w, h[u].x, bl.x));
                ay += lrelu(fmaf(w, h[u].y, bl.y));
            }
        }
        for (; i < end; i++) {
            unsigned long long e0 = __ldg(g_csr + i);
            float2 h0 = __half22float2(__ldg(reinterpret_cast<const __half2*>(
                            g_h2h + (int)(unsigned)e0 * 64 + lane * 2)));
            float w0 = __uint_as_float((unsigned)(e0 >> 32));
            ax += lrelu(fmaf(w0, h0.x, bl.x));
            ay += lrelu(fmaf(w0, h0.y, bl.y));
        }
        float deg = fmaxf((float)(end - start), 1.f);
        float2 hs = __half22float2(*reinterpret_cast<const __half2*>(g_h2h + n * 64 + lane * 2));
        ox = ax / deg + lrelu(hs.x + bl.x);
        oy = ay / deg + lrelu(hs.y + bl.y);
    }
    sp[wid][lane * 2] = ox;
    sp[wid][lane * 2 + 1] = oy;
    __syncthreads();
    if (tid < 64) {
        float s = 0.f;
#pragma unroll
        for (int w = 0; w < 8; w++) s += sp[w][tid];
        atomicAdd(&g_pool[tid], s);
    }
    __syncthreads();
    if (tid == 0) {
        __threadfence();
        unsigned t = atomicAdd(&g_tick, 1u);
        sLast = (t == gridDim.x - 1);
    }
    __syncthreads();
    if (!sLast) return;
    // last block: classifier + log_softmax, then clean state for next replay
    if (tid == 0) {
        __threadfence();
        const float inv = 1.f / (float)NN;
        float l0 = b7[0], l1 = b7[1];
#pragma unroll
        for (int j = 0; j < 64; j++) {
            float p = g_pool[j] * inv;
            l0 = fmaf(p, W7[j], l0);
            l1 = fmaf(p, W7[64 + j], l1);
        }
        float m = fmaxf(l0, l1);
        float lse = m + logf(expf(l0 - m) + expf(l1 - m));
        out[0] = l0 - lse;
        out[1] = l1 - lse;
    }
    __syncthreads();
    if (tid < 64) g_pool[tid] = 0.f;
    if (tid == 0) g_tick = 0u;
}

extern "C" void kernel_launch(void* const* d_in, const int* in_sizes, int n_in,
                              void* d_out, int out_size) {
    const float* x      = (const float*)d_in[0];
    const int*   edge   = (const int*)d_in[1];
    const float* weight = (const float*)d_in[2];
    const float* W1     = (const float*)d_in[3];
    const float* b1     = (const float*)d_in[4];
    const float* W3     = (const float*)d_in[5];
    const float* b3     = (const float*)d_in[6];
    const float* W7     = (const float*)d_in[7];
    const float* b7     = (const float*)d_in[8];
    const int E = in_sizes[2];

    const int histBlocks = (E + 255) / 256;
    k_h1hist<<<H1_BLOCKS + histBlocks, 256>>>(x, W1, edge, E);
    k_scanA<<<N_SBLK, SCAN_BLK>>>();
    k_scanB<<<N_SBLK, SCAN_BLK>>>();
    k_scatter<<<(E + 255) / 256, 256>>>(edge, weight, E);
    k_l1<<<(NN + 7) / 8, 256>>>(b1, W3);
    k_l2<<<(NN + 7) / 8, 256>>>(b3, W7, b7, (float*)d_out);
}